// round 1
// baseline (speedup 1.0000x reference)
#include <cuda_runtime.h>
#include <math.h>

#define NUM_CLASSES 10
#define PV 15                 // 5 + NUM_CLASSES floats per cell
#define CELLS_PER_BLOCK 256
#define THREADS 256
#define LAMBDA_COORD 5.0f
#define LAMBDA_NOOBJ 0.5f

// Total cells = 2048 * 26 * 26 = 1,384,448 = 5408 * 256 (exact)
#define TOTAL_CELLS (2048 * 26 * 26)
#define NUM_BLOCKS (TOTAL_CELLS / CELLS_PER_BLOCK)

// Global accumulators (coord, conf, cls) in double for safe summation.
__device__ double g_acc[3];

__global__ void yolo_init_kernel() {
    if (threadIdx.x < 3) g_acc[threadIdx.x] = 0.0;
}

__global__ __launch_bounds__(THREADS)
void yolo_main_kernel(const float* __restrict__ pred,
                      const float* __restrict__ tgt) {
    __shared__ float sp[CELLS_PER_BLOCK * PV];   // 15360 B
    __shared__ float st[CELLS_PER_BLOCK * PV];   // 15360 B
    __shared__ float red[3][THREADS / 32];

    const int nf  = CELLS_PER_BLOCK * PV;        // 3840 floats
    const long long base = (long long)blockIdx.x * nf;

    // Coalesced float4 staging of this block's contiguous chunk.
    const float4* p4 = (const float4*)(pred + base);
    const float4* t4 = (const float4*)(tgt + base);
    float4* sp4 = (float4*)sp;
    float4* st4 = (float4*)st;
    #pragma unroll 2
    for (int i = threadIdx.x; i < nf / 4; i += THREADS) {
        sp4[i] = p4[i];
        st4[i] = t4[i];
    }
    __syncthreads();

    // One cell per thread, read from SMEM (stride 15 -> conflict-free).
    const float* p = sp + threadIdx.x * PV;
    const float* t = st + threadIdx.x * PV;

    float t_conf = t[4];
    bool  obj    = t_conf > 0.0f;

    float coord_sq = 0.0f;
    #pragma unroll
    for (int k = 0; k < 4; k++) {
        float d = p[k] - t[k];
        coord_sq += d * d;
    }

    float conf_p = 1.0f / (1.0f + expf(-p[4]));

    float cls_sq = 0.0f;
    #pragma unroll
    for (int k = 5; k < 5 + NUM_CLASSES; k++) {
        float d = p[k] - t[k];
        cls_sq += d * d;
    }
    cls_sq *= (1.0f / (float)NUM_CLASSES);

    float dconf = conf_p - t_conf;
    float v_coord = obj ? LAMBDA_COORD * coord_sq : 0.0f;
    float v_conf  = obj ? dconf * dconf : LAMBDA_NOOBJ * conf_p * conf_p;
    float v_cls   = obj ? cls_sq : 0.0f;

    // Warp reduction (float partials are small: |sum| < ~2e4 per block).
    #pragma unroll
    for (int off = 16; off > 0; off >>= 1) {
        v_coord += __shfl_xor_sync(0xFFFFFFFFu, v_coord, off);
        v_conf  += __shfl_xor_sync(0xFFFFFFFFu, v_conf,  off);
        v_cls   += __shfl_xor_sync(0xFFFFFFFFu, v_cls,   off);
    }

    int lane = threadIdx.x & 31;
    int wid  = threadIdx.x >> 5;
    if (lane == 0) {
        red[0][wid] = v_coord;
        red[1][wid] = v_conf;
        red[2][wid] = v_cls;
    }
    __syncthreads();

    if (wid == 0) {
        float a = (lane < THREADS / 32) ? red[0][lane] : 0.0f;
        float b = (lane < THREADS / 32) ? red[1][lane] : 0.0f;
        float c = (lane < THREADS / 32) ? red[2][lane] : 0.0f;
        #pragma unroll
        for (int off = 4; off > 0; off >>= 1) {
            a += __shfl_xor_sync(0xFFFFFFFFu, a, off);
            b += __shfl_xor_sync(0xFFFFFFFFu, b, off);
            c += __shfl_xor_sync(0xFFFFFFFFu, c, off);
        }
        if (lane == 0) {
            atomicAdd(&g_acc[0], (double)a);
            atomicAdd(&g_acc[1], (double)b);
            atomicAdd(&g_acc[2], (double)c);
        }
    }
}

__global__ void yolo_finalize_kernel(float* __restrict__ out) {
    if (threadIdx.x == 0 && blockIdx.x == 0) {
        double c = g_acc[0], f = g_acc[1], l = g_acc[2];
        out[0] = (float)(c + f + l);   // total
        out[1] = (float)c;             // coord
        out[2] = (float)f;             // conf
        out[3] = (float)l;             // class
    }
}

extern "C" void kernel_launch(void* const* d_in, const int* in_sizes, int n_in,
                              void* d_out, int out_size) {
    const float* pred = (const float*)d_in[0];
    const float* tgt  = (const float*)d_in[1];
    float* out = (float*)d_out;

    yolo_init_kernel<<<1, 32>>>();
    yolo_main_kernel<<<NUM_BLOCKS, THREADS>>>(pred, tgt);
    yolo_finalize_kernel<<<1, 32>>>(out);
}

// round 2
// speedup vs baseline: 1.0375x; 1.0375x over previous
#include <cuda_runtime.h>
#include <math.h>

#define NUM_CLASSES 10
#define PV 15                 // 5 + NUM_CLASSES floats per cell
#define CELLS_PER_BLOCK 256
#define THREADS 256
#define LAMBDA_COORD 5.0f
#define LAMBDA_NOOBJ 0.5f

// Total cells = 2048 * 26 * 26 = 1,384,448 = 5408 * 256 (exact)
#define TOTAL_CELLS (2048 * 26 * 26)
#define NUM_BLOCKS (TOTAL_CELLS / CELLS_PER_BLOCK)

// Global accumulators (coord, conf, cls) in double + completion counter.
// Zero-initialized at module load; reset to zero by the finalizing block
// each call, so every graph replay starts from a clean state.
__device__ double g_acc[3];
__device__ unsigned int g_count;

__global__ __launch_bounds__(THREADS)
void yolo_fused_kernel(const float* __restrict__ pred,
                       const float* __restrict__ tgt,
                       float* __restrict__ out) {
    __shared__ float sp[CELLS_PER_BLOCK * PV];   // 15360 B
    __shared__ float st[CELLS_PER_BLOCK * PV];   // 15360 B
    __shared__ float red[3][THREADS / 32];
    __shared__ bool  s_is_last;

    const int nf  = CELLS_PER_BLOCK * PV;        // 3840 floats
    const long long base = (long long)blockIdx.x * nf;

    // Coalesced float4 staging of this block's contiguous chunk.
    const float4* p4 = (const float4*)(pred + base);
    const float4* t4 = (const float4*)(tgt + base);
    float4* sp4 = (float4*)sp;
    float4* st4 = (float4*)st;
    #pragma unroll 2
    for (int i = threadIdx.x; i < nf / 4; i += THREADS) {
        sp4[i] = p4[i];
        st4[i] = t4[i];
    }
    __syncthreads();

    // One cell per thread, read from SMEM (stride 15 -> conflict-free).
    const float* p = sp + threadIdx.x * PV;
    const float* t = st + threadIdx.x * PV;

    float t_conf = t[4];
    bool  obj    = t_conf > 0.0f;

    float coord_sq = 0.0f;
    #pragma unroll
    for (int k = 0; k < 4; k++) {
        float d = p[k] - t[k];
        coord_sq += d * d;
    }

    float conf_p = 1.0f / (1.0f + __expf(-p[4]));

    float cls_sq = 0.0f;
    #pragma unroll
    for (int k = 5; k < 5 + NUM_CLASSES; k++) {
        float d = p[k] - t[k];
        cls_sq += d * d;
    }
    cls_sq *= (1.0f / (float)NUM_CLASSES);

    float dconf = conf_p - t_conf;
    float v_coord = obj ? LAMBDA_COORD * coord_sq : 0.0f;
    float v_conf  = obj ? dconf * dconf : LAMBDA_NOOBJ * conf_p * conf_p;
    float v_cls   = obj ? cls_sq : 0.0f;

    // Warp reduction.
    #pragma unroll
    for (int off = 16; off > 0; off >>= 1) {
        v_coord += __shfl_xor_sync(0xFFFFFFFFu, v_coord, off);
        v_conf  += __shfl_xor_sync(0xFFFFFFFFu, v_conf,  off);
        v_cls   += __shfl_xor_sync(0xFFFFFFFFu, v_cls,   off);
    }

    int lane = threadIdx.x & 31;
    int wid  = threadIdx.x >> 5;
    if (lane == 0) {
        red[0][wid] = v_coord;
        red[1][wid] = v_conf;
        red[2][wid] = v_cls;
    }
    __syncthreads();

    if (threadIdx.x == 0) {
        float a = 0.0f, b = 0.0f, c = 0.0f;
        #pragma unroll
        for (int w = 0; w < THREADS / 32; w++) {
            a += red[0][w];
            b += red[1][w];
            c += red[2][w];
        }
        atomicAdd(&g_acc[0], (double)a);
        atomicAdd(&g_acc[1], (double)b);
        atomicAdd(&g_acc[2], (double)c);
        // Make this block's contributions globally visible before signaling.
        __threadfence();
        unsigned int prev = atomicAdd(&g_count, 1u);
        s_is_last = (prev == (unsigned int)(NUM_BLOCKS - 1));
    }
    __syncthreads();

    // Last block to finish: finalize output and reset state for next replay.
    if (s_is_last && threadIdx.x == 0) {
        volatile double* acc = g_acc;
        double c = acc[0], f = acc[1], l = acc[2];
        out[0] = (float)(c + f + l);   // total
        out[1] = (float)c;             // coord
        out[2] = (float)f;             // conf
        out[3] = (float)l;             // class
        // Reset for the next graph replay (kernel completion flushes these).
        g_acc[0] = 0.0;
        g_acc[1] = 0.0;
        g_acc[2] = 0.0;
        g_count  = 0u;
    }
}

extern "C" void kernel_launch(void* const* d_in, const int* in_sizes, int n_in,
                              void* d_out, int out_size) {
    const float* pred = (const float*)d_in[0];
    const float* tgt  = (const float*)d_in[1];
    float* out = (float*)d_out;

    yolo_fused_kernel<<<NUM_BLOCKS, THREADS>>>(pred, tgt, out);
}

// round 3
// speedup vs baseline: 1.1883x; 1.1454x over previous
#include <cuda_runtime.h>
#include <math.h>
#include <stdint.h>

#define NUM_CLASSES 10
#define PV 15                       // floats per cell
#define THREADS 128
#define TILE_CELLS 128
#define TILE_FLOATS (TILE_CELLS * PV)   // 1920
#define TILE_F4 (TILE_FLOATS / 4)       // 480 float4 per array per tile
#define TOTAL_CELLS (2048 * 26 * 26)    // 1,384,448
#define NTILES (TOTAL_CELLS / TILE_CELLS) // 10816 (exact)
#define GRID 1036                        // 148 SMs * 7 CTAs
#define LAMBDA_COORD 5.0f
#define LAMBDA_NOOBJ 0.5f

__device__ double g_acc[3];
__device__ unsigned int g_count;

__device__ __forceinline__ void cp16(uint32_t s, const float4* g) {
    asm volatile("cp.async.cg.shared.global [%0], [%1], 16;" :: "r"(s), "l"(g));
}
#define CP_COMMIT() asm volatile("cp.async.commit_group;" ::: "memory")
#define CP_WAIT1()  asm volatile("cp.async.wait_group 1;"  ::: "memory")

__global__ __launch_bounds__(THREADS)
void yolo_fused_kernel(const float* __restrict__ pred,
                       const float* __restrict__ tgt,
                       float* __restrict__ out) {
    __shared__ float4 sp[2][TILE_F4];
    __shared__ float4 st[2][TILE_F4];
    __shared__ float red[3][THREADS / 32];
    __shared__ bool  s_is_last;

    const uint32_t sp_s = (uint32_t)__cvta_generic_to_shared(&sp[0][0]);
    const uint32_t st_s = (uint32_t)__cvta_generic_to_shared(&st[0][0]);
    const int tid = threadIdx.x;

    float acc0 = 0.0f, acc1 = 0.0f, acc2 = 0.0f;

    // Prefetch first tile into buffer 0.
    int t = blockIdx.x;   // GRID < NTILES, always valid
    {
        const float4* p4 = (const float4*)pred + (size_t)t * TILE_F4;
        const float4* t4 = (const float4*)tgt  + (size_t)t * TILE_F4;
        for (int i = tid; i < TILE_F4; i += THREADS) {
            cp16(sp_s + (uint32_t)i * 16u, p4 + i);
            cp16(st_s + (uint32_t)i * 16u, t4 + i);
        }
        CP_COMMIT();
    }

    int k = 0;
    for (; t < NTILES; t += GRID, k++) {
        // Prefetch next tile into the other buffer (issued before waiting,
        // so its DRAM traffic overlaps this tile's compute).
        const int tn = t + GRID;
        const int nb = (k + 1) & 1;
        if (tn < NTILES) {
            const float4* p4 = (const float4*)pred + (size_t)tn * TILE_F4;
            const float4* t4 = (const float4*)tgt  + (size_t)tn * TILE_F4;
            const uint32_t off = (uint32_t)(nb * TILE_F4) * 16u;
            for (int i = tid; i < TILE_F4; i += THREADS) {
                cp16(sp_s + off + (uint32_t)i * 16u, p4 + i);
                cp16(st_s + off + (uint32_t)i * 16u, t4 + i);
            }
        }
        CP_COMMIT();          // (empty group if no next tile — completes instantly)
        CP_WAIT1();           // current tile's group is now complete
        __syncthreads();

        // Compute: one cell per thread, stride-15 SMEM reads (conflict-free).
        const int buf = k & 1;
        const float* p = (const float*)&sp[buf][0] + tid * PV;
        const float* q = (const float*)&st[buf][0] + tid * PV;

        float t_conf = q[4];
        bool  obj    = t_conf > 0.0f;

        float coord_sq = 0.0f;
        #pragma unroll
        for (int j = 0; j < 4; j++) {
            float d = p[j] - q[j];
            coord_sq += d * d;
        }

        float conf_p = 1.0f / (1.0f + __expf(-p[4]));

        float cls_sq = 0.0f;
        #pragma unroll
        for (int j = 5; j < 5 + NUM_CLASSES; j++) {
            float d = p[j] - q[j];
            cls_sq += d * d;
        }
        cls_sq *= (1.0f / (float)NUM_CLASSES);

        float dconf = conf_p - t_conf;
        acc0 += obj ? LAMBDA_COORD * coord_sq : 0.0f;
        acc1 += obj ? dconf * dconf : LAMBDA_NOOBJ * conf_p * conf_p;
        acc2 += obj ? cls_sq : 0.0f;

        __syncthreads();      // all reads done before this buffer is refilled
    }

    // Block reduction of per-thread partials.
    #pragma unroll
    for (int off = 16; off > 0; off >>= 1) {
        acc0 += __shfl_xor_sync(0xFFFFFFFFu, acc0, off);
        acc1 += __shfl_xor_sync(0xFFFFFFFFu, acc1, off);
        acc2 += __shfl_xor_sync(0xFFFFFFFFu, acc2, off);
    }
    const int lane = tid & 31;
    const int wid  = tid >> 5;
    if (lane == 0) {
        red[0][wid] = acc0;
        red[1][wid] = acc1;
        red[2][wid] = acc2;
    }
    __syncthreads();

    if (tid == 0) {
        float a = 0.0f, b = 0.0f, c = 0.0f;
        #pragma unroll
        for (int w = 0; w < THREADS / 32; w++) {
            a += red[0][w]; b += red[1][w]; c += red[2][w];
        }
        atomicAdd(&g_acc[0], (double)a);
        atomicAdd(&g_acc[1], (double)b);
        atomicAdd(&g_acc[2], (double)c);
        __threadfence();
        unsigned int prev = atomicAdd(&g_count, 1u);
        s_is_last = (prev == (unsigned int)(GRID - 1));
    }
    __syncthreads();

    // Last block finalizes output and resets state for the next graph replay.
    if (s_is_last && tid == 0) {
        volatile double* acc = g_acc;
        double c = acc[0], f = acc[1], l = acc[2];
        out[0] = (float)(c + f + l);   // total
        out[1] = (float)c;             // coord
        out[2] = (float)f;             // conf
        out[3] = (float)l;             // class
        g_acc[0] = 0.0;
        g_acc[1] = 0.0;
        g_acc[2] = 0.0;
        g_count  = 0u;
    }
}

extern "C" void kernel_launch(void* const* d_in, const int* in_sizes, int n_in,
                              void* d_out, int out_size) {
    const float* pred = (const float*)d_in[0];
    const float* tgt  = (const float*)d_in[1];
    float* out = (float*)d_out;

    yolo_fused_kernel<<<GRID, THREADS>>>(pred, tgt, out);
}